// round 3
// baseline (speedup 1.0000x reference)
#include <cuda_runtime.h>

#define MAXN 100000
#define MAXE 1600000
#define D    128

// ---------------- scratch (static __device__ — no allocations) ----------------
__device__ float g_bufA[(size_t)MAXN * D];   // h (GEMM output)
__device__ float g_bufB[(size_t)MAXN * D];   // agg layer1 / gemm2 input
__device__ float g_bufC[(size_t)MAXN * D];   // agg layer2
__device__ float g_dinv[MAXN];
__device__ int   g_counts[MAXN];
__device__ int   g_cursor[MAXN];
__device__ int   g_rowptr[MAXN + 1];
__device__ int   g_bsums[128];
__device__ int   g_ecol[MAXE];
__device__ float g_ew[MAXE];
__device__ int   g_src[MAXE];
__device__ int   g_dst[MAXE];
__device__ int   g_batch[MAXN];
__device__ int   g_is64;

// ---------------- dtype detection + normalization ----------------
// int64 values < 100000: every odd 32-bit word is zero. int32 random values: impossible.
__global__ void k_detect(const unsigned int* __restrict__ w) {
    __shared__ unsigned int s;
    if (threadIdx.x == 0) s = 0u;
    __syncthreads();
    unsigned int v = 0u;
    for (int i = threadIdx.x; i < 4096; i += 256) v |= w[2 * i + 1];
    atomicOr(&s, v);
    __syncthreads();
    if (threadIdx.x == 0) g_is64 = (s == 0u) ? 1 : 0;
}

__global__ void k_cvt_edges(const void* __restrict__ edges, int E) {
    int e = blockIdx.x * blockDim.x + threadIdx.x;
    if (e >= E) return;
    if (g_is64) {
        const long long* p = (const long long*)edges;
        g_src[e] = (int)p[e];
        g_dst[e] = (int)p[e + E];
    } else {
        const int* p = (const int*)edges;
        g_src[e] = p[e];
        g_dst[e] = p[e + E];
    }
}

__global__ void k_cvt_batch(const void* __restrict__ b, int N) {
    int i = blockIdx.x * blockDim.x + threadIdx.x;
    if (i >= N) return;
    if (g_is64) g_batch[i] = (int)((const long long*)b)[i];
    else        g_batch[i] = ((const int*)b)[i];
}

// ---------------- degree / CSR build ----------------
__global__ void k_zero(int N) {
    int i = blockIdx.x * blockDim.x + threadIdx.x;
    if (i < N) { g_counts[i] = 0; g_cursor[i] = 0; }
}

__global__ void k_hist(int E) {
    int e = blockIdx.x * blockDim.x + threadIdx.x;
    if (e < E) atomicAdd(&g_counts[g_dst[e]], 1);
}

__global__ void k_dinv(int N) {
    int i = blockIdx.x * blockDim.x + threadIdx.x;
    if (i < N) g_dinv[i] = rsqrtf((float)g_counts[i] + 1.0f);
}

// exclusive scan: per-block Hillis-Steele over 1024, then block sums, then add
__global__ void k_scan_block(int N) {
    __shared__ int s[1024];
    int tid = threadIdx.x;
    int i = blockIdx.x * 1024 + tid;
    int v = (i < N) ? g_counts[i] : 0;
    s[tid] = v;
    __syncthreads();
    for (int off = 1; off < 1024; off <<= 1) {
        int t = (tid >= off) ? s[tid - off] : 0;
        __syncthreads();
        s[tid] += t;
        __syncthreads();
    }
    if (i < N) g_rowptr[i] = s[tid] - v;          // exclusive
    if (tid == 1023) g_bsums[blockIdx.x] = s[1023];
}

__global__ void k_scan_sums(int nb) {
    __shared__ int s[128];
    int tid = threadIdx.x;
    int v = (tid < nb) ? g_bsums[tid] : 0;
    s[tid] = v;
    __syncthreads();
    for (int off = 1; off < 128; off <<= 1) {
        int t = (tid >= off) ? s[tid - off] : 0;
        __syncthreads();
        s[tid] += t;
        __syncthreads();
    }
    if (tid < nb) g_bsums[tid] = s[tid] - v;      // exclusive
}

__global__ void k_scan_add(int N, int E) {
    int i = blockIdx.x * blockDim.x + threadIdx.x;
    if (i < N) g_rowptr[i] += g_bsums[i >> 10];
    if (i == 0) g_rowptr[N] = E;
}

__global__ void k_fill(int E) {
    int e = blockIdx.x * blockDim.x + threadIdx.x;
    if (e >= E) return;
    int s = g_src[e], d = g_dst[e];
    int pos = atomicAdd(&g_cursor[d], 1);
    int idx = g_rowptr[d] + pos;
    g_ecol[idx] = s;
    g_ew[idx] = g_dinv[s] * g_dinv[d];
}

// ---------------- GEMM: H = X @ W  (128x128 W), AGG = H * dinv^2 ----------------
// block: 256 threads, tile 64 rows x 128 cols; thread = 4 rows x 8 cols
__global__ void __launch_bounds__(256) k_gemm(const float* __restrict__ X,
                                              const float* __restrict__ W,
                                              float* __restrict__ H,
                                              float* __restrict__ AGG,
                                              int N) {
    const int tid  = threadIdx.x;
    const int ry   = tid >> 4;          // 0..15
    const int cx   = tid & 15;          // 0..15
    const int row0 = blockIdx.x * 64 + ry * 4;
    const int cb   = cx * 8;

    float acc[4][8];
#pragma unroll
    for (int i = 0; i < 4; i++)
#pragma unroll
        for (int j = 0; j < 8; j++) acc[i][j] = 0.0f;

    const float* xr[4];
#pragma unroll
    for (int i = 0; i < 4; i++) {
        int r = row0 + i;
        if (r >= N) r = N - 1;          // clamp: safe address, result masked on store
        xr[i] = X + (size_t)r * D;
    }

#pragma unroll 8
    for (int k = 0; k < D; k++) {
        const float4 b0 = *reinterpret_cast<const float4*>(W + k * D + cb);
        const float4 b1 = *reinterpret_cast<const float4*>(W + k * D + cb + 4);
#pragma unroll
        for (int i = 0; i < 4; i++) {
            float a = __ldg(xr[i] + k);
            acc[i][0] = fmaf(a, b0.x, acc[i][0]);
            acc[i][1] = fmaf(a, b0.y, acc[i][1]);
            acc[i][2] = fmaf(a, b0.z, acc[i][2]);
            acc[i][3] = fmaf(a, b0.w, acc[i][3]);
            acc[i][4] = fmaf(a, b1.x, acc[i][4]);
            acc[i][5] = fmaf(a, b1.y, acc[i][5]);
            acc[i][6] = fmaf(a, b1.z, acc[i][6]);
            acc[i][7] = fmaf(a, b1.w, acc[i][7]);
        }
    }

#pragma unroll
    for (int i = 0; i < 4; i++) {
        int r = row0 + i;
        if (r < N) {
            float dv  = g_dinv[r];
            float dv2 = dv * dv;
            float* hp = H   + (size_t)r * D + cb;
            float* ap = AGG + (size_t)r * D + cb;
            float4 h0 = make_float4(acc[i][0], acc[i][1], acc[i][2], acc[i][3]);
            float4 h1 = make_float4(acc[i][4], acc[i][5], acc[i][6], acc[i][7]);
            *reinterpret_cast<float4*>(hp)     = h0;
            *reinterpret_cast<float4*>(hp + 4) = h1;
            *reinterpret_cast<float4*>(ap)     =
                make_float4(h0.x * dv2, h0.y * dv2, h0.z * dv2, h0.w * dv2);
            *reinterpret_cast<float4*>(ap + 4) =
                make_float4(h1.x * dv2, h1.y * dv2, h1.z * dv2, h1.w * dv2);
        }
    }
}

// ---------------- gather aggregation: AGG[d] += sum_e w[e] * H[src[e]] ----------------
// one warp per dst node; lane owns a float4 (4 feats)
__global__ void __launch_bounds__(256) k_gather(const float4* __restrict__ H4,
                                                float4* __restrict__ A4,
                                                int N) {
    int gw   = (blockIdx.x * blockDim.x + threadIdx.x) >> 5;
    int lane = threadIdx.x & 31;
    if (gw >= N) return;
    int beg = g_rowptr[gw], end = g_rowptr[gw + 1];
    float4 acc = A4[(size_t)gw * 32 + lane];
    int j = beg;
    for (; j + 2 <= end; j += 2) {
        int   s0 = __ldg(&g_ecol[j]);
        int   s1 = __ldg(&g_ecol[j + 1]);
        float w0 = __ldg(&g_ew[j]);
        float w1 = __ldg(&g_ew[j + 1]);
        float4 h0 = H4[(size_t)s0 * 32 + lane];
        float4 h1 = H4[(size_t)s1 * 32 + lane];
        acc.x = fmaf(h0.x, w0, acc.x); acc.y = fmaf(h0.y, w0, acc.y);
        acc.z = fmaf(h0.z, w0, acc.z); acc.w = fmaf(h0.w, w0, acc.w);
        acc.x = fmaf(h1.x, w1, acc.x); acc.y = fmaf(h1.y, w1, acc.y);
        acc.z = fmaf(h1.z, w1, acc.z); acc.w = fmaf(h1.w, w1, acc.w);
    }
    if (j < end) {
        int   s0 = __ldg(&g_ecol[j]);
        float w0 = __ldg(&g_ew[j]);
        float4 h0 = H4[(size_t)s0 * 32 + lane];
        acc.x = fmaf(h0.x, w0, acc.x); acc.y = fmaf(h0.y, w0, acc.y);
        acc.z = fmaf(h0.z, w0, acc.z); acc.w = fmaf(h0.w, w0, acc.w);
    }
    A4[(size_t)gw * 32 + lane] = acc;
}

// ---------------- elementwise bias + relu (between layers) ----------------
__global__ void k_bias_relu(float* __restrict__ A, const float* __restrict__ b, int n4) {
    int i = blockIdx.x * blockDim.x + threadIdx.x;
    if (i >= n4) return;
    float4 v = reinterpret_cast<float4*>(A)[i];
    float4 bb = reinterpret_cast<const float4*>(b)[i & 31];
    v.x = fmaxf(v.x + bb.x, 0.0f);
    v.y = fmaxf(v.y + bb.y, 0.0f);
    v.z = fmaxf(v.z + bb.z, 0.0f);
    v.w = fmaxf(v.w + bb.w, 0.0f);
    reinterpret_cast<float4*>(A)[i] = v;
}

// ---------------- fused global-mean-pool (+b2,relu) + MLP head ----------------
// one block (128 thr) per graph; batch is sorted -> binary search segment bounds
__global__ void __launch_bounds__(128) k_pool_mlp(const float* __restrict__ AGG,
                                                  const float* __restrict__ b2,
                                                  int Nnodes,
                                                  const float* __restrict__ Wm1,
                                                  const float* __restrict__ bm1,
                                                  const float* __restrict__ Wm2,
                                                  const float* __restrict__ bm2,
                                                  const float* __restrict__ Wm3,
                                                  const float* __restrict__ bm3,
                                                  float* __restrict__ out) {
    const int g = blockIdx.x;
    const int tid = threadIdx.x;
    __shared__ int sb[2];
    __shared__ float gs[128];
    __shared__ float a1[500];
    __shared__ float a2[100];
    __shared__ float red[128];

    if (tid < 2) {
        int target = g + tid;
        int lo = 0, hi = Nnodes;
        while (lo < hi) {
            int mid = (lo + hi) >> 1;
            if (g_batch[mid] < target) lo = mid + 1; else hi = mid;
        }
        sb[tid] = lo;
    }
    __syncthreads();
    int beg = sb[0], end = sb[1];
    int cnt = end - beg;

    float bb = b2[tid];
    float sum = 0.0f;
    for (int n = beg; n < end; n++)
        sum += fmaxf(AGG[(size_t)n * D + tid] + bb, 0.0f);
    gs[tid] = sum / (float)max(cnt, 1);
    __syncthreads();

    for (int o = tid; o < 500; o += 128) {
        float acc = bm1[o];
#pragma unroll 4
        for (int j = 0; j < 128; j++)
            acc = fmaf(gs[j], Wm1[j * 500 + o], acc);
        a1[o] = fmaxf(acc, 0.0f);
    }
    __syncthreads();

    if (tid < 100) {
        float acc = bm2[tid];
        for (int j = 0; j < 500; j++)
            acc = fmaf(a1[j], Wm2[j * 100 + tid], acc);
        a2[tid] = fmaxf(acc, 0.0f);
    }
    __syncthreads();

    red[tid] = (tid < 100) ? a2[tid] * Wm3[tid] : 0.0f;
    __syncthreads();
    for (int s = 64; s > 0; s >>= 1) {
        if (tid < s) red[tid] += red[tid + s];
        __syncthreads();
    }
    if (tid == 0) out[g] = red[0] + bm3[0];
}

// ---------------- launch ----------------
extern "C" void kernel_launch(void* const* d_in, const int* in_sizes, int n_in,
                              void* d_out, int out_size) {
    const float* x     = (const float*)d_in[0];
    const void*  edges = d_in[1];
    const void*  batch = d_in[2];
    const float* W1  = (const float*)d_in[3];
    const float* b1  = (const float*)d_in[4];
    const float* W2  = (const float*)d_in[5];
    const float* b2  = (const float*)d_in[6];
    const float* Wm1 = (const float*)d_in[7];
    const float* bm1 = (const float*)d_in[8];
    const float* Wm2 = (const float*)d_in[9];
    const float* bm2 = (const float*)d_in[10];
    const float* Wm3 = (const float*)d_in[11];
    const float* bm3 = (const float*)d_in[12];
    float* out = (float*)d_out;

    const int N = in_sizes[0] / D;
    const int E = in_sizes[1] / 2;
    const int G = out_size;

    float *bufA = nullptr, *bufB = nullptr, *bufC = nullptr;
    cudaGetSymbolAddress((void**)&bufA, g_bufA);
    cudaGetSymbolAddress((void**)&bufB, g_bufB);
    cudaGetSymbolAddress((void**)&bufC, g_bufC);

    const int tB = 256;
    const int nodeB  = (N + tB - 1) / tB;
    const int edgeB  = (E + tB - 1) / tB;
    const int scanNb = (N + 1023) / 1024;
    const int gemmB  = (N + 63) / 64;
    const int warpB  = (N * 32 + tB - 1) / tB;   // 1 warp/node
    const int ewB    = (N * 32 + tB - 1) / tB;   // N*32 float4s

    // dtype normalize
    k_detect<<<1, 256>>>((const unsigned int*)edges);
    k_cvt_edges<<<edgeB, tB>>>(edges, E);
    k_cvt_batch<<<nodeB, tB>>>(batch, N);

    // CSR build + normalization weights
    k_zero<<<nodeB, tB>>>(N);
    k_hist<<<edgeB, tB>>>(E);
    k_dinv<<<nodeB, tB>>>(N);
    k_scan_block<<<scanNb, 1024>>>(N);
    k_scan_sums<<<1, 128>>>(scanNb);
    k_scan_add<<<nodeB, tB>>>(N, E);
    k_fill<<<edgeB, tB>>>(E);

    // layer 1
    k_gemm<<<gemmB, tB>>>(x, W1, bufA, bufB, N);
    k_gather<<<warpB, tB>>>((const float4*)bufA, (float4*)bufB, N);
    k_bias_relu<<<ewB, tB>>>(bufB, b1, N * 32);

    // layer 2
    k_gemm<<<gemmB, tB>>>(bufB, W2, bufA, bufC, N);
    k_gather<<<warpB, tB>>>((const float4*)bufA, (float4*)bufC, N);

    // pool + MLP head
    k_pool_mlp<<<G, 128>>>(bufC, b2, N, Wm1, bm1, Wm2, bm2, Wm3, bm3, out);
}

// round 4
// speedup vs baseline: 1.1130x; 1.1130x over previous
#include <cuda_runtime.h>

#define MAXN 100000
#define MAXE 1600000
#define D    128

// ---------------- scratch (static __device__ — no allocations) ----------------
__device__ float g_bufA[(size_t)MAXN * D];   // H (GEMM output)
__device__ float g_bufB[(size_t)MAXN * D];   // agg layer1 (gemm2 input)
__device__ float g_bufC[(size_t)MAXN * D];   // agg layer2 (pool input)
__device__ float g_dinv[MAXN];
__device__ int   g_counts[MAXN];
__device__ int   g_cursor[MAXN];
__device__ int   g_rowptr[MAXN + 1];
__device__ int   g_bsums[128];
__device__ int2  g_epack[MAXE];              // (src col, weight bits)
__device__ int   g_src[MAXE];
__device__ int   g_dst[MAXE];
__device__ int   g_batch[MAXN];
__device__ int   g_is64;

// packed f32x2 FMA (Blackwell FFMA2 — only reachable via PTX fma.rn.f32x2)
#define FMA_F32X2(d, a, b) \
    asm("fma.rn.f32x2 %0, %1, %2, %0;" : "+l"(d) : "l"(a), "l"(b))

// ---------------- dtype detection ----------------
// int64 indices < 100000: every odd 32-bit word is zero; impossible for random int32.
__global__ void k_detect(const unsigned int* __restrict__ w) {
    __shared__ unsigned int s;
    if (threadIdx.x == 0) s = 0u;
    __syncthreads();
    unsigned int v = 0u;
    for (int i = threadIdx.x; i < 4096; i += 256) v |= w[2 * i + 1];
    atomicOr(&s, v);
    __syncthreads();
    if (threadIdx.x == 0) g_is64 = (s == 0u) ? 1 : 0;
}

__global__ void k_zero_counts(int N) {
    int i = blockIdx.x * blockDim.x + threadIdx.x;
    if (i < N) g_counts[i] = 0;
}

// convert edges + degree histogram + convert batch, one pass over E threads
__global__ void k_prep(const void* __restrict__ edges, const void* __restrict__ batch,
                       int E, int N) {
    int e = blockIdx.x * blockDim.x + threadIdx.x;
    if (e < E) {
        int s, d;
        if (g_is64) {
            const long long* p = (const long long*)edges;
            s = (int)p[e]; d = (int)p[e + E];
        } else {
            const int* p = (const int*)edges;
            s = p[e]; d = p[e + E];
        }
        g_src[e] = s; g_dst[e] = d;
        atomicAdd(&g_counts[d], 1);
    }
    if (e < N) {
        if (g_is64) g_batch[e] = (int)((const long long*)batch)[e];
        else        g_batch[e] = ((const int*)batch)[e];
    }
}

// exclusive scan over counts (also emits dinv = rsqrt(deg+1))
__global__ void k_scan_block(int N) {
    __shared__ int s[1024];
    int tid = threadIdx.x;
    int i = blockIdx.x * 1024 + tid;
    int v = (i < N) ? g_counts[i] : 0;
    if (i < N) g_dinv[i] = rsqrtf((float)v + 1.0f);
    s[tid] = v;
    __syncthreads();
    for (int off = 1; off < 1024; off <<= 1) {
        int t = (tid >= off) ? s[tid - off] : 0;
        __syncthreads();
        s[tid] += t;
        __syncthreads();
    }
    if (i < N) g_rowptr[i] = s[tid] - v;          // exclusive
    if (tid == 1023) g_bsums[blockIdx.x] = s[1023];
}

__global__ void k_scan_sums(int nb) {
    __shared__ int s[128];
    int tid = threadIdx.x;
    int v = (tid < nb) ? g_bsums[tid] : 0;
    s[tid] = v;
    __syncthreads();
    for (int off = 1; off < 128; off <<= 1) {
        int t = (tid >= off) ? s[tid - off] : 0;
        __syncthreads();
        s[tid] += t;
        __syncthreads();
    }
    if (tid < nb) g_bsums[tid] = s[tid] - v;      // exclusive
}

__global__ void k_scan_add(int N, int E) {
    int i = blockIdx.x * blockDim.x + threadIdx.x;
    if (i < N) { g_rowptr[i] += g_bsums[i >> 10]; g_cursor[i] = 0; }
    if (i == 0) g_rowptr[N] = E;
}

__global__ void k_fill(int E) {
    int e = blockIdx.x * blockDim.x + threadIdx.x;
    if (e >= E) return;
    int s = g_src[e], d = g_dst[e];
    int pos = atomicAdd(&g_cursor[d], 1);
    g_epack[g_rowptr[d] + pos] = make_int2(s, __float_as_int(g_dinv[s] * g_dinv[d]));
}

// ---------------- GEMM: H = X @ W via packed f32x2 FMA ----------------
// block 256 threads, tile 64 rows x 128 cols; thread = 4 rows x 8 cols (4 f32x2 pairs)
__global__ void __launch_bounds__(256) k_gemm(const float* __restrict__ X,
                                              const float* __restrict__ W,
                                              float* __restrict__ H,
                                              int N) {
    const int tid  = threadIdx.x;
    const int ry   = tid >> 4;          // 0..15
    const int cx   = tid & 15;          // 0..15
    const int row0 = blockIdx.x * 64 + ry * 4;
    const int cb   = cx * 8;

    unsigned long long acc[4][4];       // [row][pair] — each u64 = two f32
#pragma unroll
    for (int i = 0; i < 4; i++)
#pragma unroll
        for (int j = 0; j < 4; j++) acc[i][j] = 0ull;

    const float4* x4[4];
#pragma unroll
    for (int i = 0; i < 4; i++) {
        int r = row0 + i;
        if (r >= N) r = N - 1;          // clamp: safe address, masked on store
        x4[i] = reinterpret_cast<const float4*>(X + (size_t)r * D);
    }

    const unsigned long long* wp = reinterpret_cast<const unsigned long long*>(W + cb);

#pragma unroll 4
    for (int kc = 0; kc < 32; kc++) {
        float4 a0 = __ldg(x4[0] + kc);
        float4 a1 = __ldg(x4[1] + kc);
        float4 a2 = __ldg(x4[2] + kc);
        float4 a3 = __ldg(x4[3] + kc);
#pragma unroll
        for (int kk = 0; kk < 4; kk++) {
            unsigned long long w0, w1, w2, w3;
            asm("ld.global.nc.v2.u64 {%0,%1}, [%2];" : "=l"(w0), "=l"(w1) : "l"(wp));
            asm("ld.global.nc.v2.u64 {%0,%1}, [%2];" : "=l"(w2), "=l"(w3) : "l"(wp + 2));
            wp += 64;                   // next k row (512 B)
            float v0 = (kk == 0) ? a0.x : (kk == 1) ? a0.y : (kk == 2) ? a0.z : a0.w;
            float v1 = (kk == 0) ? a1.x : (kk == 1) ? a1.y : (kk == 2) ? a1.z : a1.w;
            float v2 = (kk == 0) ? a2.x : (kk == 1) ? a2.y : (kk == 2) ? a2.z : a2.w;
            float v3 = (kk == 0) ? a3.x : (kk == 1) ? a3.y : (kk == 2) ? a3.z : a3.w;
            unsigned long long p0, p1, p2, p3;
            asm("mov.b64 %0, {%1,%1};" : "=l"(p0) : "f"(v0));
            asm("mov.b64 %0, {%1,%1};" : "=l"(p1) : "f"(v1));
            asm("mov.b64 %0, {%1,%1};" : "=l"(p2) : "f"(v2));
            asm("mov.b64 %0, {%1,%1};" : "=l"(p3) : "f"(v3));
            FMA_F32X2(acc[0][0], p0, w0); FMA_F32X2(acc[0][1], p0, w1);
            FMA_F32X2(acc[0][2], p0, w2); FMA_F32X2(acc[0][3], p0, w3);
            FMA_F32X2(acc[1][0], p1, w0); FMA_F32X2(acc[1][1], p1, w1);
            FMA_F32X2(acc[1][2], p1, w2); FMA_F32X2(acc[1][3], p1, w3);
            FMA_F32X2(acc[2][0], p2, w0); FMA_F32X2(acc[2][1], p2, w1);
            FMA_F32X2(acc[2][2], p2, w2); FMA_F32X2(acc[2][3], p2, w3);
            FMA_F32X2(acc[3][0], p3, w0); FMA_F32X2(acc[3][1], p3, w1);
            FMA_F32X2(acc[3][2], p3, w2); FMA_F32X2(acc[3][3], p3, w3);
        }
    }

#pragma unroll
    for (int i = 0; i < 4; i++) {
        int r = row0 + i;
        if (r < N) {
            float o[8];
#pragma unroll
            for (int j = 0; j < 4; j++)
                asm("mov.b64 {%0,%1}, %2;" : "=f"(o[2*j]), "=f"(o[2*j+1]) : "l"(acc[i][j]));
            float* hp = H + (size_t)r * D + cb;
            *reinterpret_cast<float4*>(hp)     = make_float4(o[0], o[1], o[2], o[3]);
            *reinterpret_cast<float4*>(hp + 4) = make_float4(o[4], o[5], o[6], o[7]);
        }
    }
}

// ---------------- gather: A[d] = selfterm + sum_e w[e]*H[src[e]]  (+bias,relu) ----------------
// one warp per dst node; lane owns a float4 (4 feats)
template <bool RELU>
__global__ void __launch_bounds__(256) k_gather(const float4* __restrict__ H4,
                                                float4* __restrict__ A4,
                                                const float* __restrict__ bias,
                                                int N) {
    int gw   = (blockIdx.x * blockDim.x + threadIdx.x) >> 5;
    int lane = threadIdx.x & 31;
    if (gw >= N) return;
    int beg = g_rowptr[gw], end = g_rowptr[gw + 1];

    float dv  = g_dinv[gw];
    float dv2 = dv * dv;
    float4 h  = H4[(size_t)gw * 32 + lane];
    float4 acc = make_float4(h.x * dv2, h.y * dv2, h.z * dv2, h.w * dv2);

    int j = beg;
    for (; j + 4 <= end; j += 4) {
        int2 m0 = __ldg(&g_epack[j]);
        int2 m1 = __ldg(&g_epack[j + 1]);
        int2 m2 = __ldg(&g_epack[j + 2]);
        int2 m3 = __ldg(&g_epack[j + 3]);
        float4 h0 = H4[(size_t)m0.x * 32 + lane];
        float4 h1 = H4[(size_t)m1.x * 32 + lane];
        float4 h2 = H4[(size_t)m2.x * 32 + lane];
        float4 h3 = H4[(size_t)m3.x * 32 + lane];
        float w0 = __int_as_float(m0.y), w1 = __int_as_float(m1.y);
        float w2 = __int_as_float(m2.y), w3 = __int_as_float(m3.y);
        acc.x = fmaf(h0.x, w0, acc.x); acc.y = fmaf(h0.y, w0, acc.y);
        acc.z = fmaf(h0.z, w0, acc.z); acc.w = fmaf(h0.w, w0, acc.w);
        acc.x = fmaf(h1.x, w1, acc.x); acc.y = fmaf(h1.y, w1, acc.y);
        acc.z = fmaf(h1.z, w1, acc.z); acc.w = fmaf(h1.w, w1, acc.w);
        acc.x = fmaf(h2.x, w2, acc.x); acc.y = fmaf(h2.y, w2, acc.y);
        acc.z = fmaf(h2.z, w2, acc.z); acc.w = fmaf(h2.w, w2, acc.w);
        acc.x = fmaf(h3.x, w3, acc.x); acc.y = fmaf(h3.y, w3, acc.y);
        acc.z = fmaf(h3.z, w3, acc.z); acc.w = fmaf(h3.w, w3, acc.w);
    }
    for (; j < end; j++) {
        int2 m = __ldg(&g_epack[j]);
        float4 hh = H4[(size_t)m.x * 32 + lane];
        float w = __int_as_float(m.y);
        acc.x = fmaf(hh.x, w, acc.x); acc.y = fmaf(hh.y, w, acc.y);
        acc.z = fmaf(hh.z, w, acc.z); acc.w = fmaf(hh.w, w, acc.w);
    }

    if (RELU) {
        float4 bb = reinterpret_cast<const float4*>(bias)[lane];
        acc.x = fmaxf(acc.x + bb.x, 0.0f);
        acc.y = fmaxf(acc.y + bb.y, 0.0f);
        acc.z = fmaxf(acc.z + bb.z, 0.0f);
        acc.w = fmaxf(acc.w + bb.w, 0.0f);
    }
    A4[(size_t)gw * 32 + lane] = acc;
}

// ---------------- fused global-mean-pool (+b2,relu) + MLP head ----------------
__global__ void __launch_bounds__(128) k_pool_mlp(const float* __restrict__ AGG,
                                                  const float* __restrict__ b2,
                                                  int Nnodes,
                                                  const float* __restrict__ Wm1,
                                                  const float* __restrict__ bm1,
                                                  const float* __restrict__ Wm2,
                                                  const float* __restrict__ bm2,
                                                  const float* __restrict__ Wm3,
                                                  const float* __restrict__ bm3,
                                                  float* __restrict__ out) {
    const int g = blockIdx.x;
    const int tid = threadIdx.x;
    __shared__ int sb[2];
    __shared__ float gs[128];
    __shared__ float a1[500];
    __shared__ float a2[100];
    __shared__ float red[128];

    if (tid < 2) {
        int target = g + tid;
        int lo = 0, hi = Nnodes;
        while (lo < hi) {
            int mid = (lo + hi) >> 1;
            if (g_batch[mid] < target) lo = mid + 1; else hi = mid;
        }
        sb[tid] = lo;
    }
    __syncthreads();
    int beg = sb[0], end = sb[1];
    int cnt = end - beg;

    float bb = b2[tid];
    float sum = 0.0f;
#pragma unroll 4
    for (int n = beg; n < end; n++)
        sum += fmaxf(AGG[(size_t)n * D + tid] + bb, 0.0f);
    gs[tid] = sum / (float)max(cnt, 1);
    __syncthreads();

    for (int o = tid; o < 500; o += 128) {
        float acc = bm1[o];
#pragma unroll 4
        for (int j = 0; j < 128; j++)
            acc = fmaf(gs[j], Wm1[j * 500 + o], acc);
        a1[o] = fmaxf(acc, 0.0f);
    }
    __syncthreads();

    if (tid < 100) {
        float acc = bm2[tid];
        for (int j = 0; j < 500; j++)
            acc = fmaf(a1[j], Wm2[j * 100 + tid], acc);
        a2[tid] = fmaxf(acc, 0.0f);
    }
    __syncthreads();

    red[tid] = (tid < 100) ? a2[tid] * Wm3[tid] : 0.0f;
    __syncthreads();
    for (int s = 64; s > 0; s >>= 1) {
        if (tid < s) red[tid] += red[tid + s];
        __syncthreads();
    }
    if (tid == 0) out[g] = red[0] + bm3[0];
}

// ---------------- launch ----------------
extern "C" void kernel_launch(void* const* d_in, const int* in_sizes, int n_in,
                              void* d_out, int out_size) {
    const float* x     = (const float*)d_in[0];
    const void*  edges = d_in[1];
    const void*  batch = d_in[2];
    const float* W1  = (const float*)d_in[3];
    const float* b1  = (const float*)d_in[4];
    const float* W2  = (const float*)d_in[5];
    const float* b2  = (const float*)d_in[6];
    const float* Wm1 = (const float*)d_in[7];
    const float* bm1 = (const float*)d_in[8];
    const float* Wm2 = (const float*)d_in[9];
    const float* bm2 = (const float*)d_in[10];
    const float* Wm3 = (const float*)d_in[11];
    const float* bm3 = (const float*)d_in[12];
    float* out = (float*)d_out;

    const int N = in_sizes[0] / D;
    const int E = in_sizes[1] / 2;
    const int G = out_size;

    float *bufA = nullptr, *bufB = nullptr, *bufC = nullptr;
    cudaGetSymbolAddress((void**)&bufA, g_bufA);
    cudaGetSymbolAddress((void**)&bufB, g_bufB);
    cudaGetSymbolAddress((void**)&bufC, g_bufC);

    const int tB = 256;
    const int nodeB  = (N + tB - 1) / tB;
    const int edgeB  = (E + tB - 1) / tB;
    const int scanNb = (N + 1023) / 1024;
    const int gemmB  = (N + 63) / 64;
    const int warpB  = (N * 32 + tB - 1) / tB;   // 1 warp/node

    // CSR build + dtype normalize
    k_zero_counts<<<nodeB, tB>>>(N);
    k_detect<<<1, 256>>>((const unsigned int*)edges);
    k_prep<<<edgeB, tB>>>(edges, batch, E, N);
    k_scan_block<<<scanNb, 1024>>>(N);
    k_scan_sums<<<1, 128>>>(scanNb);
    k_scan_add<<<nodeB, tB>>>(N, E);
    k_fill<<<edgeB, tB>>>(E);

    // layer 1: GEMM (edge-independent) then gather with fused self-term + bias + relu
    k_gemm<<<gemmB, tB>>>(x, W1, bufA, N);
    k_gather<true><<<warpB, tB>>>((const float4*)bufA, (float4*)bufB, b1, N);

    // layer 2
    k_gemm<<<gemmB, tB>>>(bufB, W2, bufA, N);
    k_gather<false><<<warpB, tB>>>((const float4*)bufA, (float4*)bufC, nullptr, N);

    // pool + MLP head (applies b2 + relu)
    k_pool_mlp<<<G, 128>>>(bufC, b2, N, Wm1, bm1, Wm2, bm2, Wm3, bm3, out);
}